// round 2
// baseline (speedup 1.0000x reference)
#include <cuda_runtime.h>

// ModulatedConv2D as implicit GEMM.
//   M = B*H*W = 131072  (m = ((b*128)+h)*128 + w)
//   N = Cout  = 256
//   K = 9*Cin = 2304    (k = (kh*3+kw)*256 + ci)  -- matches (KH,KW,Cin,Cout) layout
// A[m][k] = x[b, h+kh-1, w+kw-1, ci] * style[b][ci]  (0 outside image)
// Bmat[k][n] = kernel reshaped (contiguous, no rearrangement)
// epilogue: out = acc * demod[b][co],  demod = rsqrt(sum_ci style^2 * sum_taps k^2 + eps)

#define BATCH 8
#define HH    128
#define WW    128
#define CIN   256
#define COUT  256
#define KTOT  2304   // 9 * CIN

__device__ float g_demod[BATCH * COUT];

// ---------------------------------------------------------------------------
// demod precompute: one block per batch sample, one thread per Cout channel.
// ---------------------------------------------------------------------------
__global__ void demod_kernel(const float* __restrict__ style,
                             const float* __restrict__ kern) {
    int b  = blockIdx.x;
    int co = threadIdx.x;
    float acc = 0.0f;
    for (int ci = 0; ci < CIN; ++ci) {
        float s  = style[b * CIN + ci];
        float s2 = s * s;
        float wsum = 0.0f;
        #pragma unroll
        for (int tap = 0; tap < 9; ++tap) {
            float w = kern[(tap * CIN + ci) * COUT + co];
            wsum = fmaf(w, w, wsum);
        }
        acc = fmaf(s2, wsum, acc);
    }
    g_demod[b * COUT + co] = rsqrtf(acc + 1e-7f);
}

// ---------------------------------------------------------------------------
// Implicit-GEMM conv. 128x128 output tile per block, BK=8, 256 threads,
// 8x8 register microtile per thread. Style modulation fused into A load,
// demod fused into epilogue.
// ---------------------------------------------------------------------------
__global__ __launch_bounds__(256) void conv_kernel(
    const float* __restrict__ x,
    const float* __restrict__ style,
    const float* __restrict__ kern,
    float* __restrict__ out) {

    __shared__ __align__(16) float As[8][128];   // As[k][m]  (transposed)
    __shared__ __align__(16) float Bs[8][128];   // Bs[k][n]

    const int tid = threadIdx.x;
    const int m0  = blockIdx.x * 128;
    const int n0  = blockIdx.y * 128;

    // microtile thread coords
    const int tx = tid & 15;   // n-direction, 16 threads
    const int ty = tid >> 4;   // m-direction, 16 threads

    // A-tile load mapping: one float4 per thread. 128 rows x 2 float4-cols.
    const int a_row  = tid >> 1;          // 0..127
    const int a_col4 = (tid & 1) * 4;     // 0 or 4
    const int m_ld = m0 + a_row;
    const int bb   = m_ld >> 14;          // batch of this loader row
    const int hy   = (m_ld >> 7) & 127;
    const int wx   = m_ld & 127;

    // B-tile load mapping: 8 rows x 32 float4-cols.
    const int b_row  = tid >> 5;          // 0..7
    const int b_col4 = (tid & 31) * 4;    // 0..124

    float acc[8][8];
    #pragma unroll
    for (int i = 0; i < 8; ++i)
        #pragma unroll
        for (int j = 0; j < 8; ++j) acc[i][j] = 0.0f;

    for (int k0 = 0; k0 < KTOT; k0 += 8) {
        // BK=8 slice never crosses a tap boundary (256 % 8 == 0):
        const int tap = k0 >> 8;          // 0..8, fixed within this slice
        const int kh  = tap / 3;
        const int kw  = tap - kh * 3;
        const int ci0 = k0 & 255;

        // ---- load A slice (with SAME padding + style modulation) ----
        const int ih = hy + kh - 1;
        const int iw = wx + kw - 1;
        float4 av = make_float4(0.f, 0.f, 0.f, 0.f);
        if ((unsigned)ih < (unsigned)HH && (unsigned)iw < (unsigned)WW) {
            const float4 xv = *(const float4*)(
                x + ((((size_t)bb * HH + ih) * WW + iw) * CIN + ci0 + a_col4));
            const float4 sv = *(const float4*)(style + bb * CIN + ci0 + a_col4);
            av.x = xv.x * sv.x; av.y = xv.y * sv.y;
            av.z = xv.z * sv.z; av.w = xv.w * sv.w;
        }
        As[a_col4 + 0][a_row] = av.x;
        As[a_col4 + 1][a_row] = av.y;
        As[a_col4 + 2][a_row] = av.z;
        As[a_col4 + 3][a_row] = av.w;

        // ---- load B slice (weights, contiguous) ----
        const float4 bv = *(const float4*)(
            kern + (size_t)(k0 + b_row) * COUT + n0 + b_col4);
        *(float4*)&Bs[b_row][b_col4] = bv;

        __syncthreads();

        // ---- rank-8 update ----
        #pragma unroll
        for (int kk = 0; kk < 8; ++kk) {
            float afr[8], bfr[8];
            *(float4*)(&afr[0]) = *(const float4*)(&As[kk][ty * 8]);
            *(float4*)(&afr[4]) = *(const float4*)(&As[kk][ty * 8 + 4]);
            *(float4*)(&bfr[0]) = *(const float4*)(&Bs[kk][tx * 8]);
            *(float4*)(&bfr[4]) = *(const float4*)(&Bs[kk][tx * 8 + 4]);
            #pragma unroll
            for (int i = 0; i < 8; ++i)
                #pragma unroll
                for (int j = 0; j < 8; ++j)
                    acc[i][j] = fmaf(afr[i], bfr[j], acc[i][j]);
        }
        __syncthreads();
    }

    // ---- epilogue: demodulate and store ----
    const int bblk = m0 >> 14;   // all 128 rows of this block share one batch
    float dm[8];
    #pragma unroll
    for (int j = 0; j < 8; ++j)
        dm[j] = g_demod[bblk * COUT + n0 + tx * 8 + j];

    #pragma unroll
    for (int i = 0; i < 8; ++i) {
        const int m = m0 + ty * 8 + i;
        float* op = out + (size_t)m * COUT + n0 + tx * 8;
        float4 v0, v1;
        v0.x = acc[i][0] * dm[0]; v0.y = acc[i][1] * dm[1];
        v0.z = acc[i][2] * dm[2]; v0.w = acc[i][3] * dm[3];
        v1.x = acc[i][4] * dm[4]; v1.y = acc[i][5] * dm[5];
        v1.z = acc[i][6] * dm[6]; v1.w = acc[i][7] * dm[7];
        *(float4*)(op)     = v0;
        *(float4*)(op + 4) = v1;
    }
}

// ---------------------------------------------------------------------------
extern "C" void kernel_launch(void* const* d_in, const int* in_sizes, int n_in,
                              void* d_out, int out_size) {
    const float* x     = (const float*)d_in[0];   // (8,128,128,256) f32
    const float* style = (const float*)d_in[1];   // (8,256) f32
    const float* kern  = (const float*)d_in[2];   // (3,3,256,256) f32
    float* out = (float*)d_out;                   // (8,128,128,256) f32

    demod_kernel<<<BATCH, COUT>>>(style, kern);

    dim3 grid((BATCH * HH * WW) / 128, COUT / 128);  // (1024, 2)
    conv_kernel<<<grid, 256>>>(x, style, kern, out);
}

// round 7
// speedup vs baseline: 1.7854x; 1.7854x over previous
#include <cuda_runtime.h>
#include <cuda_bf16.h>
#include <cstdint>

#define BATCH 8
#define HH    128
#define WW    128
#define CIN   256
#define COUT  256
#define KTOT  2304           // 9 * CIN
#define NKC   72             // 2304 / 32
#define STAGES 3
#define STAGE_BYTES 32768    // Ahi 8K + Alo 8K + Bhi 8K + Blo 8K
#define SMEM_BYTES (STAGES * STAGE_BYTES)

// ---------------- static device scratch ----------------
__device__ float g_demod[BATCH * COUT];
__device__ __align__(16) __nv_bfloat16 g_xhi[BATCH * HH * WW * CIN]; // x*style hi
__device__ __align__(16) __nv_bfloat16 g_xlo[BATCH * HH * WW * CIN]; // x*style lo
__device__ __align__(16) __nv_bfloat16 g_whi[KTOT * COUT];           // weights hi [k][n]
__device__ __align__(16) __nv_bfloat16 g_wlo[KTOT * COUT];           // weights lo [k][n]

// ---------------- PTX helpers (all plain sm_80-class) ----------------
static __device__ __forceinline__ uint32_t s2u(const void* p) {
    uint32_t a;
    asm("{ .reg .u64 t; cvta.to.shared.u64 t, %1; cvt.u32.u64 %0, t; }"
        : "=r"(a) : "l"(p));
    return a;
}
static __device__ __forceinline__ void cpasync(uint32_t dst, const void* src,
                                               uint32_t srcsz) {
    asm volatile("cp.async.cg.shared.global [%0], [%1], 16, %2;"
                 :: "r"(dst), "l"(src), "r"(srcsz) : "memory");
}
#define CP_COMMIT() asm volatile("cp.async.commit_group;" ::: "memory")
#define CP_WAIT1()  asm volatile("cp.async.wait_group 1;" ::: "memory")

static __device__ __forceinline__ void ldsm4(uint32_t* r, uint32_t a) {
    asm volatile("ldmatrix.sync.aligned.m8n8.x4.shared.b16 {%0,%1,%2,%3}, [%4];"
                 : "=r"(r[0]), "=r"(r[1]), "=r"(r[2]), "=r"(r[3]) : "r"(a));
}
static __device__ __forceinline__ void ldsm4t(uint32_t* r, uint32_t a) {
    asm volatile("ldmatrix.sync.aligned.m8n8.x4.trans.shared.b16 {%0,%1,%2,%3}, [%4];"
                 : "=r"(r[0]), "=r"(r[1]), "=r"(r[2]), "=r"(r[3]) : "r"(a));
}
static __device__ __forceinline__ void mma16816(float* c, const uint32_t* a,
                                                uint32_t b0, uint32_t b1) {
    asm volatile(
        "mma.sync.aligned.m16n8k16.row.col.f32.bf16.bf16.f32 "
        "{%0,%1,%2,%3}, {%4,%5,%6,%7}, {%8,%9}, {%0,%1,%2,%3};"
        : "+f"(c[0]), "+f"(c[1]), "+f"(c[2]), "+f"(c[3])
        : "r"(a[0]), "r"(a[1]), "r"(a[2]), "r"(a[3]), "r"(b0), "r"(b1));
}

// ---------------- pre-pass kernels ----------------
__global__ void demod_kernel(const float* __restrict__ style,
                             const float* __restrict__ kern) {
    int b  = blockIdx.x;
    int co = threadIdx.x;
    float acc = 0.0f;
    for (int ci = 0; ci < CIN; ++ci) {
        float s = style[b * CIN + ci];
        float wsum = 0.0f;
        #pragma unroll
        for (int tap = 0; tap < 9; ++tap) {
            float w = kern[(tap * CIN + ci) * COUT + co];
            wsum = fmaf(w, w, wsum);
        }
        acc = fmaf(s * s, wsum, acc);
    }
    g_demod[b * COUT + co] = rsqrtf(acc + 1e-7f);
}

__global__ __launch_bounds__(256) void split_x_kernel(
    const float* __restrict__ x, const float* __restrict__ style) {
    size_t e = ((size_t)blockIdx.x * 256 + threadIdx.x) * 4;
    int ci = (int)(e & 255);
    int b  = (int)(e >> 22);
    float4 xv = *(const float4*)(x + e);
    float4 sv = *(const float4*)(style + b * CIN + ci);
    float m[4] = {xv.x * sv.x, xv.y * sv.y, xv.z * sv.z, xv.w * sv.w};
    uint32_t hi01, hi23, lo01, lo23;
    {
        __nv_bfloat16 h0 = __float2bfloat16(m[0]);
        __nv_bfloat16 h1 = __float2bfloat16(m[1]);
        __nv_bfloat16 h2 = __float2bfloat16(m[2]);
        __nv_bfloat16 h3 = __float2bfloat16(m[3]);
        __nv_bfloat16 l0 = __float2bfloat16(m[0] - __bfloat162float(h0));
        __nv_bfloat16 l1 = __float2bfloat16(m[1] - __bfloat162float(h1));
        __nv_bfloat16 l2 = __float2bfloat16(m[2] - __bfloat162float(h2));
        __nv_bfloat16 l3 = __float2bfloat16(m[3] - __bfloat162float(h3));
        hi01 = ((uint32_t)__bfloat16_as_ushort(h1) << 16) | __bfloat16_as_ushort(h0);
        hi23 = ((uint32_t)__bfloat16_as_ushort(h3) << 16) | __bfloat16_as_ushort(h2);
        lo01 = ((uint32_t)__bfloat16_as_ushort(l1) << 16) | __bfloat16_as_ushort(l0);
        lo23 = ((uint32_t)__bfloat16_as_ushort(l3) << 16) | __bfloat16_as_ushort(l2);
    }
    *(uint2*)(g_xhi + e) = make_uint2(hi01, hi23);
    *(uint2*)(g_xlo + e) = make_uint2(lo01, lo23);
}

__global__ void split_w_kernel(const float* __restrict__ kern) {
    int i = blockIdx.x * 256 + threadIdx.x;    // i = k*COUT + n (layout matches!)
    if (i >= KTOT * COUT) return;
    float w = kern[i];
    __nv_bfloat16 hv = __float2bfloat16(w);
    g_whi[i] = hv;
    g_wlo[i] = __float2bfloat16(w - __bfloat162float(hv));
}

// ---------------- main mma.sync kernel ----------------
// CTA tile 128(M) x 128(N) x 32(K). 8 warps: wm in {0,1} (64 rows each),
// wn in {0..3} (32 cols each). 3 products per K-slice: AhiBhi, AhiBlo, AloBhi.
// smem stage layout: Ahi @0, Alo @8K, Bhi @16K, Blo @24K.
// A swizzle: 128 rows x 4 chunks(16B): chunk' = c ^ ((row>>1)&3)
// B swizzle: 32 rows x 16 chunks:      chunk' = c ^ (row&7)
__global__ __launch_bounds__(256, 1) void conv_mma_kernel(float* __restrict__ out) {
    extern __shared__ char dsm[];
    const uint32_t smem = s2u(dsm);
    const int tid  = threadIdx.x;
    const int wid  = tid >> 5;
    const int lane = tid & 31;
    const int wm = wid & 1;          // M warp coord
    const int wn = wid >> 1;         // N warp coord
    const int mt = blockIdx.x;       // 0..1023, 128 consecutive m = one image row
    const int n0 = blockIdx.y * 128;
    const int b  = mt >> 7;
    const int h  = mt & 127;
    const int m0 = mt * 128;

    // loader constants
    const int arow = tid >> 1;          // 0..127 = w pixel
    const int ac0  = (tid & 1) * 2;     // A chunk base (2 chunks per thread)
    const int brow = tid >> 3;          // 0..31 = k row
    const int bc0  = (tid & 7) * 2;     // B chunk base

    auto load_stage = [&](int kc, int stage) {
        const uint32_t sb = smem + (uint32_t)stage * STAGE_BYTES;
        const int tap = kc >> 3;
        const int ci0 = (kc & 7) << 5;
        const int dh  = tap / 3;
        const int dw  = tap - dh * 3;
        const int ih  = h + dh - 1;
        const int iw  = arow + dw - 1;
        const bool v  = ((unsigned)ih < HH) && ((unsigned)iw < WW);
        const uint32_t sz = v ? 16u : 0u;
        const size_t gA = (((size_t)b * HH + (v ? ih : 0)) * WW + (v ? iw : 0)) * CIN + ci0;
        const uint32_t da = sb + (uint32_t)arow * 64u;
        #pragma unroll
        for (int j = 0; j < 2; ++j) {
            int c = ac0 + j;
            uint32_t off = (uint32_t)((c ^ ((arow >> 1) & 3)) * 16);
            cpasync(da + off,         g_xhi + gA + c * 8, sz);
            cpasync(da + 8192u + off, g_xlo + gA + c * 8, sz);
        }
        const size_t gB = (size_t)(kc * 32 + brow) * COUT + n0;
        const uint32_t db = sb + 16384u + (uint32_t)brow * 256u;
        #pragma unroll
        for (int j = 0; j < 2; ++j) {
            int c = bc0 + j;
            uint32_t off = (uint32_t)((c ^ (brow & 7)) * 16);
            cpasync(db + off,         g_whi + gB + c * 8, 16u);
            cpasync(db + 8192u + off, g_wlo + gB + c * 8, 16u);
        }
    };

    // ldmatrix lane constants
    const int lr = lane & 7;        // row within 8-group
    const int lg = lane >> 3;       // group 0..3
    const int cg = lg >> 1;         // chunk half select
    // A: rows for 4 m-blocks
    int rowA[4];
    #pragma unroll
    for (int mb = 0; mb < 4; ++mb)
        rowA[mb] = wm * 64 + mb * 16 + lr + (lg & 1) * 8;
    // B: k rows per kstep
    const int rkb = (lg & 1) * 8 + lr;

    float acc[4][4][4];
    #pragma unroll
    for (int mb = 0; mb < 4; ++mb)
        #pragma unroll
        for (int nb = 0; nb < 4; ++nb)
            #pragma unroll
            for (int q = 0; q < 4; ++q) acc[mb][nb][q] = 0.0f;

    // prologue
    load_stage(0, 0); CP_COMMIT();
    load_stage(1, 1); CP_COMMIT();

    for (int kc = 0; kc < NKC; ++kc) {
        CP_WAIT1();
        __syncthreads();
        const int nk = kc + STAGES - 1;
        if (nk < NKC) load_stage(nk, nk % STAGES);
        CP_COMMIT();

        const uint32_t sb = smem + (uint32_t)(kc % STAGES) * STAGE_BYTES;
        #pragma unroll
        for (int ks = 0; ks < 2; ++ks) {
            uint32_t a[4][4], bh[2][4], bt[2][4];
            // Ahi fragments
            #pragma unroll
            for (int mb = 0; mb < 4; ++mb) {
                int ch = 2 * ks + cg;
                ldsm4(a[mb], sb + (uint32_t)(rowA[mb] * 64 +
                             ((ch ^ ((rowA[mb] >> 1) & 3)) * 16)));
            }
            // Bhi fragments (2 x ldmatrix.x4.trans cover n=32)
            #pragma unroll
            for (int h2 = 0; h2 < 2; ++h2) {
                int rk = ks * 16 + rkb;
                int ch = wn * 4 + h2 * 2 + cg;
                ldsm4t(bh[h2], sb + 16384u + (uint32_t)(rk * 256 +
                               ((ch ^ (rk & 7)) * 16)));
            }
            // product 1: Ahi * Bhi
            #pragma unroll
            for (int mb = 0; mb < 4; ++mb)
                #pragma unroll
                for (int nb = 0; nb < 4; ++nb)
                    mma16816(acc[mb][nb], a[mb],
                             bh[nb >> 1][2 * (nb & 1)], bh[nb >> 1][2 * (nb & 1) + 1]);
            // Blo fragments
            #pragma unroll
            for (int h2 = 0; h2 < 2; ++h2) {
                int rk = ks * 16 + rkb;
                int ch = wn * 4 + h2 * 2 + cg;
                ldsm4t(bt[h2], sb + 24576u + (uint32_t)(rk * 256 +
                               ((ch ^ (rk & 7)) * 16)));
            }
            // product 2: Ahi * Blo
            #pragma unroll
            for (int mb = 0; mb < 4; ++mb)
                #pragma unroll
                for (int nb = 0; nb < 4; ++nb)
                    mma16816(acc[mb][nb], a[mb],
                             bt[nb >> 1][2 * (nb & 1)], bt[nb >> 1][2 * (nb & 1) + 1]);
            // Alo fragments (overwrite a)
            #pragma unroll
            for (int mb = 0; mb < 4; ++mb) {
                int ch = 2 * ks + cg;
                ldsm4(a[mb], sb + 8192u + (uint32_t)(rowA[mb] * 64 +
                             ((ch ^ ((rowA[mb] >> 1) & 3)) * 16)));
            }
            // product 3: Alo * Bhi
            #pragma unroll
            for (int mb = 0; mb < 4; ++mb)
                #pragma unroll
                for (int nb = 0; nb < 4; ++nb)
                    mma16816(acc[mb][nb], a[mb],
                             bh[nb >> 1][2 * (nb & 1)], bh[nb >> 1][2 * (nb & 1) + 1]);
        }
    }

    // ---- epilogue: demod + store ----
    const int mbase = m0 + wm * 64;
    const int nbase = n0 + wn * 32;
    const float* dmp = g_demod + b * COUT;
    float dm[4][2];
    #pragma unroll
    for (int nb = 0; nb < 4; ++nb) {
        int n = nbase + nb * 8 + (lane & 3) * 2;
        dm[nb][0] = __ldg(dmp + n);
        dm[nb][1] = __ldg(dmp + n + 1);
    }
    #pragma unroll
    for (int mb = 0; mb < 4; ++mb) {
        #pragma unroll
        for (int r2 = 0; r2 < 2; ++r2) {
            int m = mbase + mb * 16 + (lane >> 2) + r2 * 8;
            float* op = out + (size_t)m * COUT;
            #pragma unroll
            for (int nb = 0; nb < 4; ++nb) {
                int n = nbase + nb * 8 + (lane & 3) * 2;
                float2 v;
                v.x = acc[mb][nb][2 * r2]     * dm[nb][0];
                v.y = acc[mb][nb][2 * r2 + 1] * dm[nb][1];
                *(float2*)(op + n) = v;
            }
        }
    }
}

// ---------------- host launch ----------------
extern "C" void kernel_launch(void* const* d_in, const int* in_sizes, int n_in,
                              void* d_out, int out_size) {
    const float* x     = (const float*)d_in[0];   // (8,128,128,256)
    const float* style = (const float*)d_in[1];   // (8,256)
    const float* kern  = (const float*)d_in[2];   // (3,3,256,256)
    float* out = (float*)d_out;

    demod_kernel<<<BATCH, COUT>>>(style, kern);
    split_x_kernel<<<(BATCH * HH * WW * CIN) / 4 / 256, 256>>>(x, style);
    split_w_kernel<<<(KTOT * COUT + 255) / 256, 256>>>(kern);

    cudaFuncSetAttribute(conv_mma_kernel,
                         cudaFuncAttributeMaxDynamicSharedMemorySize, SMEM_BYTES);
    dim3 grid(1024, 2);
    conv_mma_kernel<<<grid, 256, SMEM_BYTES>>>(out);
}

// round 8
// speedup vs baseline: 3.3367x; 1.8689x over previous
#include <cuda_runtime.h>
#include <cuda_bf16.h>
#include <cstdint>

#define BATCH 8
#define HH    128
#define WW    128
#define CIN   256
#define COUT  256
#define KTOT  2304           // 9 * CIN
#define NKC   72             // 2304 / 32
#define STAGES 3
#define STAGE_BYTES 32768    // Ahi 8K + Alo 8K + Bhi 8K + Blo 8K
#define SMEM_BYTES (STAGES * STAGE_BYTES)

// ---------------- static device scratch ----------------
__device__ float g_demod[BATCH * COUT];
__device__ float g_k2[CIN * COUT];                                   // sum_tap w^2
__device__ __align__(16) __nv_bfloat16 g_xhi[BATCH * HH * WW * CIN]; // x*style hi
__device__ __align__(16) __nv_bfloat16 g_xlo[BATCH * HH * WW * CIN]; // x*style lo
__device__ __align__(16) __nv_bfloat16 g_whi[KTOT * COUT];           // weights hi [k][n]
__device__ __align__(16) __nv_bfloat16 g_wlo[KTOT * COUT];           // weights lo [k][n]

// ---------------- PTX helpers (all plain sm_80-class) ----------------
static __device__ __forceinline__ uint32_t s2u(const void* p) {
    uint32_t a;
    asm("{ .reg .u64 t; cvta.to.shared.u64 t, %1; cvt.u32.u64 %0, t; }"
        : "=r"(a) : "l"(p));
    return a;
}
static __device__ __forceinline__ void cpasync(uint32_t dst, const void* src,
                                               uint32_t srcsz) {
    asm volatile("cp.async.cg.shared.global [%0], [%1], 16, %2;"
                 :: "r"(dst), "l"(src), "r"(srcsz) : "memory");
}
#define CP_COMMIT() asm volatile("cp.async.commit_group;" ::: "memory")
#define CP_WAIT1()  asm volatile("cp.async.wait_group 1;" ::: "memory")

static __device__ __forceinline__ void ldsm4(uint32_t* r, uint32_t a) {
    asm volatile("ldmatrix.sync.aligned.m8n8.x4.shared.b16 {%0,%1,%2,%3}, [%4];"
                 : "=r"(r[0]), "=r"(r[1]), "=r"(r[2]), "=r"(r[3]) : "r"(a));
}
static __device__ __forceinline__ void ldsm4t(uint32_t* r, uint32_t a) {
    asm volatile("ldmatrix.sync.aligned.m8n8.x4.trans.shared.b16 {%0,%1,%2,%3}, [%4];"
                 : "=r"(r[0]), "=r"(r[1]), "=r"(r[2]), "=r"(r[3]) : "r"(a));
}
static __device__ __forceinline__ void mma16816(float* c, const uint32_t* a,
                                                uint32_t b0, uint32_t b1) {
    asm volatile(
        "mma.sync.aligned.m16n8k16.row.col.f32.bf16.bf16.f32 "
        "{%0,%1,%2,%3}, {%4,%5,%6,%7}, {%8,%9}, {%0,%1,%2,%3};"
        : "+f"(c[0]), "+f"(c[1]), "+f"(c[2]), "+f"(c[3])
        : "r"(a[0]), "r"(a[1]), "r"(a[2]), "r"(a[3]), "r"(b0), "r"(b1));
}

// ---------------- pre-pass kernels ----------------
// tap-reduction: k2[ci][co] = sum_tap w[tap][ci][co]^2   (65536 threads, coalesced)
__global__ void k2_kernel(const float* __restrict__ kern) {
    int ci = blockIdx.x;
    int co = threadIdx.x;
    float s = 0.0f;
    #pragma unroll
    for (int tap = 0; tap < 9; ++tap) {
        float w = kern[(size_t)(tap * CIN + ci) * COUT + co];
        s = fmaf(w, w, s);
    }
    g_k2[ci * COUT + co] = s;
}

// demod[b][co] = rsqrt( sum_ci style[b][ci]^2 * k2[ci][co] + eps )
__global__ void demod_kernel(const float* __restrict__ style) {
    __shared__ float s2[CIN];
    int b  = blockIdx.x;
    int co = threadIdx.x;
    float sv = style[b * CIN + co];
    s2[co] = sv * sv;
    __syncthreads();
    float acc = 0.0f;
    #pragma unroll 8
    for (int ci = 0; ci < CIN; ++ci)
        acc = fmaf(s2[ci], g_k2[ci * COUT + co], acc);
    g_demod[b * COUT + co] = rsqrtf(acc + 1e-7f);
}

__global__ __launch_bounds__(256) void split_x_kernel(
    const float* __restrict__ x, const float* __restrict__ style) {
    size_t e = ((size_t)blockIdx.x * 256 + threadIdx.x) * 4;
    int ci = (int)(e & 255);
    int b  = (int)(e >> 22);
    float4 xv = *(const float4*)(x + e);
    float4 sv = *(const float4*)(style + b * CIN + ci);
    float m[4] = {xv.x * sv.x, xv.y * sv.y, xv.z * sv.z, xv.w * sv.w};
    uint32_t hi01, hi23, lo01, lo23;
    {
        __nv_bfloat16 h0 = __float2bfloat16(m[0]);
        __nv_bfloat16 h1 = __float2bfloat16(m[1]);
        __nv_bfloat16 h2 = __float2bfloat16(m[2]);
        __nv_bfloat16 h3 = __float2bfloat16(m[3]);
        __nv_bfloat16 l0 = __float2bfloat16(m[0] - __bfloat162float(h0));
        __nv_bfloat16 l1 = __float2bfloat16(m[1] - __bfloat162float(h1));
        __nv_bfloat16 l2 = __float2bfloat16(m[2] - __bfloat162float(h2));
        __nv_bfloat16 l3 = __float2bfloat16(m[3] - __bfloat162float(h3));
        hi01 = ((uint32_t)__bfloat16_as_ushort(h1) << 16) | __bfloat16_as_ushort(h0);
        hi23 = ((uint32_t)__bfloat16_as_ushort(h3) << 16) | __bfloat16_as_ushort(h2);
        lo01 = ((uint32_t)__bfloat16_as_ushort(l1) << 16) | __bfloat16_as_ushort(l0);
        lo23 = ((uint32_t)__bfloat16_as_ushort(l3) << 16) | __bfloat16_as_ushort(l2);
    }
    *(uint2*)(g_xhi + e) = make_uint2(hi01, hi23);
    *(uint2*)(g_xlo + e) = make_uint2(lo01, lo23);
}

__global__ void split_w_kernel(const float* __restrict__ kern) {
    int i = blockIdx.x * 256 + threadIdx.x;    // i = k*COUT + n (layout matches!)
    if (i >= KTOT * COUT) return;
    float w = kern[i];
    __nv_bfloat16 hv = __float2bfloat16(w);
    g_whi[i] = hv;
    g_wlo[i] = __float2bfloat16(w - __bfloat162float(hv));
}

// ---------------- main mma.sync kernel ----------------
// CTA tile 128(M) x 128(N) x 32(K). 8 warps: wm in {0,1} (64 rows each),
// wn in {0..3} (32 cols each). 3 products per K-slice: AhiBhi, AhiBlo, AloBhi.
// smem stage layout: Ahi @0, Alo @8K, Bhi @16K, Blo @24K.
// A swizzle: 128 rows x 4 chunks(16B): chunk' = c ^ ((row>>1)&3)
// B swizzle: 32 rows x 16 chunks:      chunk' = c ^ (row&7)
// __launch_bounds__(256, 2): cap regs at 128 -> 2 CTAs/SM (smem 96K*2 fits 228K)
__global__ __launch_bounds__(256, 2) void conv_mma_kernel(float* __restrict__ out) {
    extern __shared__ char dsm[];
    const uint32_t smem = s2u(dsm);
    const int tid  = threadIdx.x;
    const int wid  = tid >> 5;
    const int lane = tid & 31;
    const int wm = wid & 1;          // M warp coord
    const int wn = wid >> 1;         // N warp coord
    const int mt = blockIdx.x;       // 0..1023, 128 consecutive m = one image row
    const int n0 = blockIdx.y * 128;
    const int b  = mt >> 7;
    const int h  = mt & 127;
    const int m0 = mt * 128;

    // loader constants
    const int arow = tid >> 1;          // 0..127 = w pixel
    const int ac0  = (tid & 1) * 2;     // A chunk base (2 chunks per thread)
    const int brow = tid >> 3;          // 0..31 = k row
    const int bc0  = (tid & 7) * 2;     // B chunk base

    auto load_stage = [&](int kc, int stage) {
        const uint32_t sb = smem + (uint32_t)stage * STAGE_BYTES;
        const int tap = kc >> 3;
        const int ci0 = (kc & 7) << 5;
        const int dh  = tap / 3;
        const int dw  = tap - dh * 3;
        const int ih  = h + dh - 1;
        const int iw  = arow + dw - 1;
        const bool v  = ((unsigned)ih < HH) && ((unsigned)iw < WW);
        const uint32_t sz = v ? 16u : 0u;
        const size_t gA = (((size_t)b * HH + (v ? ih : 0)) * WW + (v ? iw : 0)) * CIN + ci0;
        const uint32_t da = sb + (uint32_t)arow * 64u;
        #pragma unroll
        for (int j = 0; j < 2; ++j) {
            int c = ac0 + j;
            uint32_t off = (uint32_t)((c ^ ((arow >> 1) & 3)) * 16);
            cpasync(da + off,         g_xhi + gA + c * 8, sz);
            cpasync(da + 8192u + off, g_xlo + gA + c * 8, sz);
        }
        const size_t gB = (size_t)(kc * 32 + brow) * COUT + n0;
        const uint32_t db = sb + 16384u + (uint32_t)brow * 256u;
        #pragma unroll
        for (int j = 0; j < 2; ++j) {
            int c = bc0 + j;
            uint32_t off = (uint32_t)((c ^ (brow & 7)) * 16);
            cpasync(db + off,         g_whi + gB + c * 8, 16u);
            cpasync(db + 8192u + off, g_wlo + gB + c * 8, 16u);
        }
    };

    // ldmatrix lane constants
    const int lr = lane & 7;        // row within 8-group
    const int lg = lane >> 3;       // group 0..3
    const int cg = lg >> 1;         // chunk half select
    // A: rows for 4 m-blocks
    int rowA[4];
    #pragma unroll
    for (int mb = 0; mb < 4; ++mb)
        rowA[mb] = wm * 64 + mb * 16 + lr + (lg & 1) * 8;
    // B: k rows per kstep
    const int rkb = (lg & 1) * 8 + lr;

    float acc[4][4][4];
    #pragma unroll
    for (int mb = 0; mb < 4; ++mb)
        #pragma unroll
        for (int nb = 0; nb < 4; ++nb)
            #pragma unroll
            for (int q = 0; q < 4; ++q) acc[mb][nb][q] = 0.0f;

    // prologue
    load_stage(0, 0); CP_COMMIT();
    load_stage(1, 1); CP_COMMIT();

    for (int kc = 0; kc < NKC; ++kc) {
        CP_WAIT1();
        __syncthreads();
        const int nk = kc + STAGES - 1;
        if (nk < NKC) load_stage(nk, nk % STAGES);
        CP_COMMIT();

        const uint32_t sb = smem + (uint32_t)(kc % STAGES) * STAGE_BYTES;
        #pragma unroll
        for (int ks = 0; ks < 2; ++ks) {
            uint32_t a[4][4], bh[2][4], bt[2][4];
            // Ahi fragments
            #pragma unroll
            for (int mb = 0; mb < 4; ++mb) {
                int ch = 2 * ks + cg;
                ldsm4(a[mb], sb + (uint32_t)(rowA[mb] * 64 +
                             ((ch ^ ((rowA[mb] >> 1) & 3)) * 16)));
            }
            // Bhi fragments (2 x ldmatrix.x4.trans cover n=32)
            #pragma unroll
            for (int h2 = 0; h2 < 2; ++h2) {
                int rk = ks * 16 + rkb;
                int ch = wn * 4 + h2 * 2 + cg;
                ldsm4t(bh[h2], sb + 16384u + (uint32_t)(rk * 256 +
                               ((ch ^ (rk & 7)) * 16)));
            }
            // product 1: Ahi * Bhi
            #pragma unroll
            for (int mb = 0; mb < 4; ++mb)
                #pragma unroll
                for (int nb = 0; nb < 4; ++nb)
                    mma16816(acc[mb][nb], a[mb],
                             bh[nb >> 1][2 * (nb & 1)], bh[nb >> 1][2 * (nb & 1) + 1]);
            // Blo fragments
            #pragma unroll
            for (int h2 = 0; h2 < 2; ++h2) {
                int rk = ks * 16 + rkb;
                int ch = wn * 4 + h2 * 2 + cg;
                ldsm4t(bt[h2], sb + 24576u + (uint32_t)(rk * 256 +
                               ((ch ^ (rk & 7)) * 16)));
            }
            // product 2: Ahi * Blo
            #pragma unroll
            for (int mb = 0; mb < 4; ++mb)
                #pragma unroll
                for (int nb = 0; nb < 4; ++nb)
                    mma16816(acc[mb][nb], a[mb],
                             bt[nb >> 1][2 * (nb & 1)], bt[nb >> 1][2 * (nb & 1) + 1]);
            // Alo fragments (overwrite a)
            #pragma unroll
            for (int mb = 0; mb < 4; ++mb) {
                int ch = 2 * ks + cg;
                ldsm4(a[mb], sb + 8192u + (uint32_t)(rowA[mb] * 64 +
                             ((ch ^ ((rowA[mb] >> 1) & 3)) * 16)));
            }
            // product 3: Alo * Bhi
            #pragma unroll
            for (int mb = 0; mb < 4; ++mb)
                #pragma unroll
                for (int nb = 0; nb < 4; ++nb)
                    mma16816(acc[mb][nb], a[mb],
                             bh[nb >> 1][2 * (nb & 1)], bh[nb >> 1][2 * (nb & 1) + 1]);
        }
    }

    // ---- epilogue: demod + store ----
    const int mbase = m0 + wm * 64;
    const int nbase = n0 + wn * 32;
    const float* dmp = g_demod + b * COUT;
    float dm[4][2];
    #pragma unroll
    for (int nb = 0; nb < 4; ++nb) {
        int n = nbase + nb * 8 + (lane & 3) * 2;
        dm[nb][0] = __ldg(dmp + n);
        dm[nb][1] = __ldg(dmp + n + 1);
    }
    #pragma unroll
    for (int mb = 0; mb < 4; ++mb) {
        #pragma unroll
        for (int r2 = 0; r2 < 2; ++r2) {
            int m = mbase + mb * 16 + (lane >> 2) + r2 * 8;
            float* op = out + (size_t)m * COUT;
            #pragma unroll
            for (int nb = 0; nb < 4; ++nb) {
                int n = nbase + nb * 8 + (lane & 3) * 2;
                float2 v;
                v.x = acc[mb][nb][2 * r2]     * dm[nb][0];
                v.y = acc[mb][nb][2 * r2 + 1] * dm[nb][1];
                *(float2*)(op + n) = v;
            }
        }
    }
}

// ---------------- host launch ----------------
extern "C" void kernel_launch(void* const* d_in, const int* in_sizes, int n_in,
                              void* d_out, int out_size) {
    const float* x     = (const float*)d_in[0];   // (8,128,128,256)
    const float* style = (const float*)d_in[1];   // (8,256)
    const float* kern  = (const float*)d_in[2];   // (3,3,256,256)
    float* out = (float*)d_out;

    k2_kernel<<<CIN, COUT>>>(kern);
    split_x_kernel<<<(BATCH * HH * WW * CIN) / 4 / 256, 256>>>(x, style);
    split_w_kernel<<<(KTOT * COUT + 255) / 256, 256>>>(kern);
    demod_kernel<<<BATCH, COUT>>>(style);

    cudaFuncSetAttribute(conv_mma_kernel,
                         cudaFuncAttributeMaxDynamicSharedMemorySize, SMEM_BYTES);
    dim3 grid(1024, 2);
    conv_mma_kernel<<<grid, 256, SMEM_BYTES>>>(out);
}

// round 9
// speedup vs baseline: 4.5419x; 1.3612x over previous
#include <cuda_runtime.h>
#include <cuda_fp16.h>
#include <cstdint>

#define BATCH 8
#define HH    128
#define WW    128
#define CIN   256
#define COUT  256
#define KTOT  2304           // 9 * CIN
#define NKC   72             // 2304 / 32
#define STAGES 3
#define STAGE_BYTES 24576    // Ahi 8K + Alo 8K + B 8K
#define SMEM_BYTES (STAGES * STAGE_BYTES)

// ---------------- static device scratch ----------------
__device__ float g_demod[BATCH * COUT];
__device__ float g_k2t[COUT * CIN];                           // sum_tap w^2, [co][ci]
__device__ __align__(16) __half g_xhi[BATCH * HH * WW * CIN]; // x*style hi (fp16)
__device__ __align__(16) __half g_xlo[BATCH * HH * WW * CIN]; // x*style lo (fp16)
__device__ __align__(16) __half g_wh [KTOT * COUT];           // weights fp16 [k][n]

// ---------------- PTX helpers (all plain sm_80-class) ----------------
static __device__ __forceinline__ uint32_t s2u(const void* p) {
    uint32_t a;
    asm("{ .reg .u64 t; cvta.to.shared.u64 t, %1; cvt.u32.u64 %0, t; }"
        : "=r"(a) : "l"(p));
    return a;
}
static __device__ __forceinline__ void cpasync(uint32_t dst, const void* src,
                                               uint32_t srcsz) {
    asm volatile("cp.async.cg.shared.global [%0], [%1], 16, %2;"
                 :: "r"(dst), "l"(src), "r"(srcsz) : "memory");
}
#define CP_COMMIT() asm volatile("cp.async.commit_group;" ::: "memory")
#define CP_WAIT1()  asm volatile("cp.async.wait_group 1;" ::: "memory")

static __device__ __forceinline__ void ldsm4(uint32_t* r, uint32_t a) {
    asm volatile("ldmatrix.sync.aligned.m8n8.x4.shared.b16 {%0,%1,%2,%3}, [%4];"
                 : "=r"(r[0]), "=r"(r[1]), "=r"(r[2]), "=r"(r[3]) : "r"(a));
}
static __device__ __forceinline__ void ldsm4t(uint32_t* r, uint32_t a) {
    asm volatile("ldmatrix.sync.aligned.m8n8.x4.trans.shared.b16 {%0,%1,%2,%3}, [%4];"
                 : "=r"(r[0]), "=r"(r[1]), "=r"(r[2]), "=r"(r[3]) : "r"(a));
}
static __device__ __forceinline__ void mma16816(float* c, const uint32_t* a,
                                                uint32_t b0, uint32_t b1) {
    asm volatile(
        "mma.sync.aligned.m16n8k16.row.col.f32.f16.f16.f32 "
        "{%0,%1,%2,%3}, {%4,%5,%6,%7}, {%8,%9}, {%0,%1,%2,%3};"
        : "+f"(c[0]), "+f"(c[1]), "+f"(c[2]), "+f"(c[3])
        : "r"(a[0]), "r"(a[1]), "r"(a[2]), "r"(a[3]), "r"(b0), "r"(b1));
}

// ---------------- pre-pass kernels ----------------
// k2t[co][ci] = sum_tap w[tap][ci][co]^2  (transposed for coalesced demod reads)
__global__ void k2_kernel(const float* __restrict__ kern) {
    int ci = blockIdx.x;
    int co = threadIdx.x;
    float s = 0.0f;
    #pragma unroll
    for (int tap = 0; tap < 9; ++tap) {
        float w = kern[(size_t)(tap * CIN + ci) * COUT + co];
        s = fmaf(w, w, s);
    }
    g_k2t[co * CIN + ci] = s;
}

// demod[b][co] = rsqrt( sum_ci style[b][ci]^2 * k2t[co][ci] + eps )
// warp per (b,co): 2048 warps = 256 blocks x 256 threads
__global__ __launch_bounds__(256) void demod_kernel(const float* __restrict__ style) {
    int gw   = blockIdx.x * 8 + (threadIdx.x >> 5);   // 0..2047
    int lane = threadIdx.x & 31;
    int b  = gw >> 8;
    int co = gw & 255;
    float acc = 0.0f;
    #pragma unroll
    for (int t = 0; t < 8; ++t) {
        int ci = t * 32 + lane;
        float s = style[b * CIN + ci];
        acc = fmaf(s * s, g_k2t[co * CIN + ci], acc);
    }
    #pragma unroll
    for (int o = 16; o > 0; o >>= 1)
        acc += __shfl_xor_sync(0xFFFFFFFF, acc, o);
    if (lane == 0) g_demod[b * COUT + co] = rsqrtf(acc + 1e-7f);
}

__global__ __launch_bounds__(256) void split_x_kernel(
    const float* __restrict__ x, const float* __restrict__ style) {
    size_t e = ((size_t)blockIdx.x * 256 + threadIdx.x) * 4;
    int ci = (int)(e & 255);
    int b  = (int)(e >> 22);
    float4 xv = *(const float4*)(x + e);
    float4 sv = *(const float4*)(style + b * CIN + ci);
    float m[4] = {xv.x * sv.x, xv.y * sv.y, xv.z * sv.z, xv.w * sv.w};
    __half h[4], l[4];
    #pragma unroll
    for (int j = 0; j < 4; ++j) {
        h[j] = __float2half_rn(m[j]);
        l[j] = __float2half_rn(m[j] - __half2float(h[j]));
    }
    uint32_t hi01 = ((uint32_t)__half_as_ushort(h[1]) << 16) | __half_as_ushort(h[0]);
    uint32_t hi23 = ((uint32_t)__half_as_ushort(h[3]) << 16) | __half_as_ushort(h[2]);
    uint32_t lo01 = ((uint32_t)__half_as_ushort(l[1]) << 16) | __half_as_ushort(l[0]);
    uint32_t lo23 = ((uint32_t)__half_as_ushort(l[3]) << 16) | __half_as_ushort(l[2]);
    *(uint2*)(g_xhi + e) = make_uint2(hi01, hi23);
    *(uint2*)(g_xlo + e) = make_uint2(lo01, lo23);
}

__global__ void split_w_kernel(const float* __restrict__ kern) {
    int i = blockIdx.x * 256 + threadIdx.x;    // i = k*COUT + n (layout matches)
    if (i >= KTOT * COUT) return;
    g_wh[i] = __float2half_rn(kern[i]);
}

// ---------------- main mma.sync kernel ----------------
// CTA tile 128(M) x 128(N) x 32(K). 8 warps: wm in {0,1}, wn in {0..3}.
// fp16 2-product split: acc += Ahi*B + Alo*B  (B single fp16, err ~2^-11).
// smem stage: Ahi @0, Alo @8K, B @16K.
// A swizzle: 128 rows x 4 chunks(16B): chunk' = c ^ ((row>>1)&3)
// B swizzle: 32 rows x 16 chunks:      chunk' = c ^ (row&7)
__global__ __launch_bounds__(256, 2) void conv_mma_kernel(float* __restrict__ out) {
    extern __shared__ char dsm[];
    const uint32_t smem = s2u(dsm);
    const int tid  = threadIdx.x;
    const int wid  = tid >> 5;
    const int lane = tid & 31;
    const int wm = wid & 1;
    const int wn = wid >> 1;
    const int mt = blockIdx.x;       // 128 consecutive m = one image row
    const int n0 = blockIdx.y * 128;
    const int b  = mt >> 7;
    const int h  = mt & 127;
    const int m0 = mt * 128;

    const int arow = tid >> 1;          // 0..127 = w pixel
    const int ac0  = (tid & 1) * 2;     // A chunk base
    const int brow = tid >> 3;          // 0..31 = k row
    const int bc0  = (tid & 7) * 2;     // B chunk base

    auto load_stage = [&](int kc, int stage) {
        const uint32_t sb = smem + (uint32_t)stage * STAGE_BYTES;
        const int tap = kc >> 3;
        const int ci0 = (kc & 7) << 5;
        const int dh  = tap / 3;
        const int dw  = tap - dh * 3;
        const int ih  = h + dh - 1;
        const int iw  = arow + dw - 1;
        const bool v  = ((unsigned)ih < HH) && ((unsigned)iw < WW);
        const uint32_t sz = v ? 16u : 0u;
        const size_t gA = (((size_t)b * HH + (v ? ih : 0)) * WW + (v ? iw : 0)) * CIN + ci0;
        const uint32_t da = sb + (uint32_t)arow * 64u;
        #pragma unroll
        for (int j = 0; j < 2; ++j) {
            int c = ac0 + j;
            uint32_t off = (uint32_t)((c ^ ((arow >> 1) & 3)) * 16);
            cpasync(da + off,         g_xhi + gA + c * 8, sz);
            cpasync(da + 8192u + off, g_xlo + gA + c * 8, sz);
        }
        const size_t gB = (size_t)(kc * 32 + brow) * COUT + n0;
        const uint32_t db = sb + 16384u + (uint32_t)brow * 256u;
        #pragma unroll
        for (int j = 0; j < 2; ++j) {
            int c = bc0 + j;
            uint32_t off = (uint32_t)((c ^ (brow & 7)) * 16);
            cpasync(db + off, g_wh + gB + c * 8, 16u);
        }
    };

    const int lr = lane & 7;
    const int lg = lane >> 3;
    const int cg = lg >> 1;
    int rowA[4];
    #pragma unroll
    for (int mb = 0; mb < 4; ++mb)
        rowA[mb] = wm * 64 + mb * 16 + lr + (lg & 1) * 8;
    const int rkb = (lg & 1) * 8 + lr;

    float acc[4][4][4];
    #pragma unroll
    for (int mb = 0; mb < 4; ++mb)
        #pragma unroll
        for (int nb = 0; nb < 4; ++nb)
            #pragma unroll
            for (int q = 0; q < 4; ++q) acc[mb][nb][q] = 0.0f;

    load_stage(0, 0); CP_COMMIT();
    load_stage(1, 1); CP_COMMIT();

    for (int kc = 0; kc < NKC; ++kc) {
        CP_WAIT1();
        __syncthreads();
        const int nk = kc + STAGES - 1;
        if (nk < NKC) load_stage(nk, nk % STAGES);
        CP_COMMIT();

        const uint32_t sb = smem + (uint32_t)(kc % STAGES) * STAGE_BYTES;
        #pragma unroll
        for (int ks = 0; ks < 2; ++ks) {
            uint32_t a[4][4], bh[2][4];
            // Ahi fragments
            #pragma unroll
            for (int mb = 0; mb < 4; ++mb) {
                int ch = 2 * ks + cg;
                ldsm4(a[mb], sb + (uint32_t)(rowA[mb] * 64 +
                             ((ch ^ ((rowA[mb] >> 1) & 3)) * 16)));
            }
            // B fragments
            #pragma unroll
            for (int h2 = 0; h2 < 2; ++h2) {
                int rk = ks * 16 + rkb;
                int ch = wn * 4 + h2 * 2 + cg;
                ldsm4t(bh[h2], sb + 16384u + (uint32_t)(rk * 256 +
                               ((ch ^ (rk & 7)) * 16)));
            }
            // product 1: Ahi * B
            #pragma unroll
            for (int mb = 0; mb < 4; ++mb)
                #pragma unroll
                for (int nb = 0; nb < 4; ++nb)
                    mma16816(acc[mb][nb], a[mb],
                             bh[nb >> 1][2 * (nb & 1)], bh[nb >> 1][2 * (nb & 1) + 1]);
            // Alo fragments (overwrite a)
            #pragma unroll
            for (int mb = 0; mb < 4; ++mb) {
                int ch = 2 * ks + cg;
                ldsm4(a[mb], sb + 8192u + (uint32_t)(rowA[mb] * 64 +
                             ((ch ^ ((rowA[mb] >> 1) & 3)) * 16)));
            }
            // product 2: Alo * B
            #pragma unroll
            for (int mb = 0; mb < 4; ++mb)
                #pragma unroll
                for (int nb = 0; nb < 4; ++nb)
                    mma16816(acc[mb][nb], a[mb],
                             bh[nb >> 1][2 * (nb & 1)], bh[nb >> 1][2 * (nb & 1) + 1]);
        }
    }

    // ---- epilogue: demod + store ----
    const int mbase = m0 + wm * 64;
    const int nbase = n0 + wn * 32;
    const float* dmp = g_demod + b * COUT;
    float dm[4][2];
    #pragma unroll
    for (int nb = 0; nb < 4; ++nb) {
        int n = nbase + nb * 8 + (lane & 3) * 2;
        dm[nb][0] = __ldg(dmp + n);
        dm[nb][1] = __ldg(dmp + n + 1);
    }
    #pragma unroll
    for (int mb = 0; mb < 4; ++mb) {
        #pragma unroll
        for (int r2 = 0; r2 < 2; ++r2) {
            int m = mbase + mb * 16 + (lane >> 2) + r2 * 8;
            float* op = out + (size_t)m * COUT;
            #pragma unroll
            for (int nb = 0; nb < 4; ++nb) {
                int n = nbase + nb * 8 + (lane & 3) * 2;
                float2 v;
                v.x = acc[mb][nb][2 * r2]     * dm[nb][0];
                v.y = acc[mb][nb][2 * r2 + 1] * dm[nb][1];
                *(float2*)(op + n) = v;
            }
        }
    }
}

// ---------------- host launch ----------------
extern "C" void kernel_launch(void* const* d_in, const int* in_sizes, int n_in,
                              void* d_out, int out_size) {
    const float* x     = (const float*)d_in[0];   // (8,128,128,256)
    const float* style = (const float*)d_in[1];   // (8,256)
    const float* kern  = (const float*)d_in[2];   // (3,3,256,256)
    float* out = (float*)d_out;

    k2_kernel<<<CIN, COUT>>>(kern);
    split_x_kernel<<<(BATCH * HH * WW * CIN) / 4 / 256, 256>>>(x, style);
    split_w_kernel<<<(KTOT * COUT + 255) / 256, 256>>>(kern);
    demod_kernel<<<256, 256>>>(style);

    cudaFuncSetAttribute(conv_mma_kernel,
                         cudaFuncAttributeMaxDynamicSharedMemorySize, SMEM_BYTES);
    dim3 grid(1024, 2);
    conv_mma_kernel<<<grid, 256, SMEM_BYTES>>>(out);
}

// round 10
// speedup vs baseline: 8.3816x; 1.8454x over previous
#include <cuda_runtime.h>
#include <cuda_fp16.h>
#include <cstdint>

#define BATCH 8
#define HH    128
#define WW    128
#define CIN   256
#define COUT  256
#define KTOT  2304           // 9 * CIN
#define NKC   72             // 2304 / 32
#define STAGES 4
#define STAGE_BYTES 16384    // A 8K + B 8K
#define SMEM_BYTES (STAGES * STAGE_BYTES)

// ---------------- static device scratch ----------------
__device__ float g_demod[BATCH * COUT];
__device__ float g_k2t[COUT * CIN];                          // sum_tap w^2, [co][ci]
__device__ __align__(16) __half g_xh[BATCH * HH * WW * CIN]; // x*style (fp16)
__device__ __align__(16) __half g_wh[KTOT * COUT];           // weights fp16 [k][n]

// ---------------- PTX helpers (all plain sm_80-class) ----------------
static __device__ __forceinline__ uint32_t s2u(const void* p) {
    uint32_t a;
    asm("{ .reg .u64 t; cvta.to.shared.u64 t, %1; cvt.u32.u64 %0, t; }"
        : "=r"(a) : "l"(p));
    return a;
}
static __device__ __forceinline__ void cpasync(uint32_t dst, const void* src,
                                               uint32_t srcsz) {
    asm volatile("cp.async.cg.shared.global [%0], [%1], 16, %2;"
                 :: "r"(dst), "l"(src), "r"(srcsz) : "memory");
}
#define CP_COMMIT() asm volatile("cp.async.commit_group;" ::: "memory")
#define CP_WAIT2()  asm volatile("cp.async.wait_group 2;" ::: "memory")

static __device__ __forceinline__ void ldsm4(uint32_t* r, uint32_t a) {
    asm volatile("ldmatrix.sync.aligned.m8n8.x4.shared.b16 {%0,%1,%2,%3}, [%4];"
                 : "=r"(r[0]), "=r"(r[1]), "=r"(r[2]), "=r"(r[3]) : "r"(a));
}
static __device__ __forceinline__ void ldsm4t(uint32_t* r, uint32_t a) {
    asm volatile("ldmatrix.sync.aligned.m8n8.x4.trans.shared.b16 {%0,%1,%2,%3}, [%4];"
                 : "=r"(r[0]), "=r"(r[1]), "=r"(r[2]), "=r"(r[3]) : "r"(a));
}
static __device__ __forceinline__ void mma16816(float* c, const uint32_t* a,
                                                uint32_t b0, uint32_t b1) {
    asm volatile(
        "mma.sync.aligned.m16n8k16.row.col.f32.f16.f16.f32 "
        "{%0,%1,%2,%3}, {%4,%5,%6,%7}, {%8,%9}, {%0,%1,%2,%3};"
        : "+f"(c[0]), "+f"(c[1]), "+f"(c[2]), "+f"(c[3])
        : "r"(a[0]), "r"(a[1]), "r"(a[2]), "r"(a[3]), "r"(b0), "r"(b1));
}

// ---------------- pre-pass kernels ----------------
__global__ void k2_kernel(const float* __restrict__ kern) {
    int ci = blockIdx.x;
    int co = threadIdx.x;
    float s = 0.0f;
    #pragma unroll
    for (int tap = 0; tap < 9; ++tap) {
        float w = kern[(size_t)(tap * CIN + ci) * COUT + co];
        s = fmaf(w, w, s);
    }
    g_k2t[co * CIN + ci] = s;
}

__global__ __launch_bounds__(256) void demod_kernel(const float* __restrict__ style) {
    int gw   = blockIdx.x * 8 + (threadIdx.x >> 5);   // 0..2047
    int lane = threadIdx.x & 31;
    int b  = gw >> 8;
    int co = gw & 255;
    float acc = 0.0f;
    #pragma unroll
    for (int t = 0; t < 8; ++t) {
        int ci = t * 32 + lane;
        float s = style[b * CIN + ci];
        acc = fmaf(s * s, g_k2t[co * CIN + ci], acc);
    }
    #pragma unroll
    for (int o = 16; o > 0; o >>= 1)
        acc += __shfl_xor_sync(0xFFFFFFFF, acc, o);
    if (lane == 0) g_demod[b * COUT + co] = rsqrtf(acc + 1e-7f);
}

__global__ __launch_bounds__(256) void mod_x_kernel(
    const float* __restrict__ x, const float* __restrict__ style) {
    size_t e = ((size_t)blockIdx.x * 256 + threadIdx.x) * 4;
    int ci = (int)(e & 255);
    int b  = (int)(e >> 22);
    float4 xv = *(const float4*)(x + e);
    float4 sv = *(const float4*)(style + b * CIN + ci);
    __half2 p01 = __floats2half2_rn(xv.x * sv.x, xv.y * sv.y);
    __half2 p23 = __floats2half2_rn(xv.z * sv.z, xv.w * sv.w);
    *(uint2*)(g_xh + e) = make_uint2(*(uint32_t*)&p01, *(uint32_t*)&p23);
}

__global__ void conv_w_kernel(const float* __restrict__ kern) {
    int i = blockIdx.x * 256 + threadIdx.x;    // i = k*COUT + n (layout matches)
    if (i >= KTOT * COUT) return;
    g_wh[i] = __float2half_rn(kern[i]);
}

// ---------------- main mma.sync kernel ----------------
// CTA tile 128(M) x 128(N) x 32(K). 8 warps: wm in {0,1}, wn in {0..3}.
// Single-product fp16: acc += A*B (err ~sqrt(2)*2^-12 per term, ~3e-4 overall).
// smem stage: A @0 (8K), B @8K (8K). 4 stages.
// A swizzle: 128 rows x 4 chunks(16B): chunk' = c ^ ((row>>1)&3)
// B swizzle: 32 rows x 16 chunks:      chunk' = c ^ (row&7)
__global__ __launch_bounds__(256, 2) void conv_mma_kernel(float* __restrict__ out) {
    extern __shared__ char dsm[];
    const uint32_t smem = s2u(dsm);
    const int tid  = threadIdx.x;
    const int wid  = tid >> 5;
    const int lane = tid & 31;
    const int wm = wid & 1;
    const int wn = wid >> 1;
    const int mt = blockIdx.x;       // 128 consecutive m = one image row
    const int n0 = blockIdx.y * 128;
    const int b  = mt >> 7;
    const int h  = mt & 127;
    const int m0 = mt * 128;

    const int arow = tid >> 1;          // 0..127 = w pixel
    const int ac0  = (tid & 1) * 2;     // A chunk base (2 chunks of 16B)
    const int brow = tid >> 3;          // 0..31 = k row
    const int bc0  = (tid & 7) * 2;     // B chunk base

    auto load_stage = [&](int kc, int stage) {
        const uint32_t sb = smem + (uint32_t)stage * STAGE_BYTES;
        const int tap = kc >> 3;
        const int ci0 = (kc & 7) << 5;
        const int dh  = tap / 3;
        const int dw  = tap - dh * 3;
        const int ih  = h + dh - 1;
        const int iw  = arow + dw - 1;
        const bool v  = ((unsigned)ih < HH) && ((unsigned)iw < WW);
        const uint32_t sz = v ? 16u : 0u;
        const size_t gA = (((size_t)b * HH + (v ? ih : 0)) * WW + (v ? iw : 0)) * CIN + ci0;
        const uint32_t da = sb + (uint32_t)arow * 64u;
        #pragma unroll
        for (int j = 0; j < 2; ++j) {
            int c = ac0 + j;
            uint32_t off = (uint32_t)((c ^ ((arow >> 1) & 3)) * 16);
            cpasync(da + off, g_xh + gA + c * 8, sz);
        }
        const size_t gB = (size_t)(kc * 32 + brow) * COUT + n0;
        const uint32_t db = sb + 8192u + (uint32_t)brow * 256u;
        #pragma unroll
        for (int j = 0; j < 2; ++j) {
            int c = bc0 + j;
            uint32_t off = (uint32_t)((c ^ (brow & 7)) * 16);
            cpasync(db + off, g_wh + gB + c * 8, 16u);
        }
    };

    const int lr = lane & 7;
    const int lg = lane >> 3;
    const int cg = lg >> 1;
    int rowA[4];
    #pragma unroll
    for (int mb = 0; mb < 4; ++mb)
        rowA[mb] = wm * 64 + mb * 16 + lr + (lg & 1) * 8;
    const int rkb = (lg & 1) * 8 + lr;

    float acc[4][4][4];
    #pragma unroll
    for (int mb = 0; mb < 4; ++mb)
        #pragma unroll
        for (int nb = 0; nb < 4; ++nb)
            #pragma unroll
            for (int q = 0; q < 4; ++q) acc[mb][nb][q] = 0.0f;

    load_stage(0, 0); CP_COMMIT();
    load_stage(1, 1); CP_COMMIT();
    load_stage(2, 2); CP_COMMIT();

    for (int kc = 0; kc < NKC; ++kc) {
        CP_WAIT2();
        __syncthreads();
        const int nk = kc + STAGES - 1;
        if (nk < NKC) load_stage(nk, nk & (STAGES - 1));
        CP_COMMIT();

        const uint32_t sb = smem + (uint32_t)(kc & (STAGES - 1)) * STAGE_BYTES;
        #pragma unroll
        for (int ks = 0; ks < 2; ++ks) {
            uint32_t a[4][4], bh[2][4];
            #pragma unroll
            for (int mb = 0; mb < 4; ++mb) {
                int ch = 2 * ks + cg;
                ldsm4(a[mb], sb + (uint32_t)(rowA[mb] * 64 +
                             ((ch ^ ((rowA[mb] >> 1) & 3)) * 16)));
            }
            #pragma unroll
            for (int h2 = 0; h2 < 2; ++h2) {
                int rk = ks * 16 + rkb;
                int ch = wn * 4 + h2 * 2 + cg;
                ldsm4t(bh[h2], sb + 8192u + (uint32_t)(rk * 256 +
                               ((ch ^ (rk & 7)) * 16)));
            }
            #pragma unroll
            for (int mb = 0; mb < 4; ++mb)
                #pragma unroll
                for (int nb = 0; nb < 4; ++nb)
                    mma16816(acc[mb][nb], a[mb],
                             bh[nb >> 1][2 * (nb & 1)], bh[nb >> 1][2 * (nb & 1) + 1]);
        }
        __syncthreads();
    }

    // ---- epilogue: demod + store ----
    const int mbase = m0 + wm * 64;
    const int nbase = n0 + wn * 32;
    const float* dmp = g_demod + b * COUT;
    float dm[4][2];
    #pragma unroll
    for (int nb = 0; nb < 4; ++nb) {
        int n = nbase + nb * 8 + (lane & 3) * 2;
        dm[nb][0] = __ldg(dmp + n);
        dm[nb][1] = __ldg(dmp + n + 1);
    }
    #pragma unroll
    for (int mb = 0; mb < 4; ++mb) {
        #pragma unroll
        for (int r2 = 0; r2 < 2; ++r2) {
            int m = mbase + mb * 16 + (lane >> 2) + r2 * 8;
            float* op = out + (size_t)m * COUT;
            #pragma unroll
            for (int nb = 0; nb < 4; ++nb) {
                int n = nbase + nb * 8 + (lane & 3) * 2;
                float2 v;
                v.x = acc[mb][nb][2 * r2]     * dm[nb][0];
                v.y = acc[mb][nb][2 * r2 + 1] * dm[nb][1];
                *(float2*)(op + n) = v;
            }
        }
    }
}

// ---------------- host launch ----------------
extern "C" void kernel_launch(void* const* d_in, const int* in_sizes, int n_in,
                              void* d_out, int out_size) {
    const float* x     = (const float*)d_in[0];   // (8,128,128,256)
    const float* style = (const float*)d_in[1];   // (8,256)
    const float* kern  = (const float*)d_in[2];   // (3,3,256,256)
    float* out = (float*)d_out;

    k2_kernel<<<CIN, COUT>>>(kern);
    mod_x_kernel<<<(BATCH * HH * WW * CIN) / 4 / 256, 256>>>(x, style);
    conv_w_kernel<<<(KTOT * COUT + 255) / 256, 256>>>(kern);
    demod_kernel<<<256, 256>>>(style);

    cudaFuncSetAttribute(conv_mma_kernel,
                         cudaFuncAttributeMaxDynamicSharedMemorySize, SMEM_BYTES);
    dim3 grid(1024, 2);
    conv_mma_kernel<<<grid, 256, SMEM_BYTES>>>(out);
}